// round 13
// baseline (speedup 1.0000x reference)
#include <cuda_runtime.h>
#include <cuda_fp16.h>

// 2-layer GCN via CSC build + gather aggregation.
// edge_index arrives as int32 (JAX x64 disabled).
// h' = (x@W1)*dinv stored FP16 (128B/row), fp32 accumulation, s' = s*dinv.
// No init kernel: device globals start zeroed; k_layer2 re-zeroes
// g_pack/g_scanstate at the end of every call.
// k_edge_count -> k_scan -> k_gemmfill(INTERLEAVED roles) -> k_layer1 -> k_layer2
//
// k_gemmfill: blockIdx%3==0 -> gemm (FMA-bound), else -> fill (L2-bound).
// Interleaving puts both block types in every wave so the pipes overlap.

#define N_NODES 100000
#define N_EDGES 1600000
#define C 64
#define SCAN_B 256
#define NB ((N_NODES + SCAN_B - 1) / SCAN_B)   // 391
#define W_SCALE 67108864.0f                    // 2^26 fixed-point for w
#define W_MASK  ((1ULL << 40) - 1ULL)
#define GB 64
#define GEMM_GRID ((N_NODES + GB - 1) / GB)    // 1563
#define GF_GRID (GEMM_GRID * 3)                // 4689: 1563 gemm + 3126 fill slots

__device__ unsigned long long g_pack[N_NODES];   // {cnt:24 | sum_w fixed:40}
__device__ float g_dinv[N_NODES];
__device__ int   g_off[N_NODES + 1];
__device__ unsigned long long g_scanstate[NB];   // {flag:2 | value:32}
__device__ __align__(16) unsigned g_rank[N_EDGES];
__device__ __align__(16) uint2 g_edge[N_EDGES];            // {src, w bits}
__device__ __align__(16) __half g_hh[(size_t)N_NODES * C]; // h' fp16, 128B/row
__device__ float g_s[N_NODES];                             // s' = s*dinv

__device__ __forceinline__ unsigned h2_bits(__half2 v) {
    return *reinterpret_cast<unsigned*>(&v);
}

// one packed u64 atomic per edge; prev count == rank within destination bucket
__global__ void k_edge_count(const int* __restrict__ ei,
                             const float* __restrict__ w) {
    int t = blockIdx.x * blockDim.x + threadIdx.x;
    if (t * 2 >= N_EDGES) return;
    int2   cc = *reinterpret_cast<const int2*>(ei + N_EDGES + t * 2);
    float2 ww = *reinterpret_cast<const float2*>(w + t * 2);
    unsigned long long p0 = (1ULL << 40) + (unsigned long long)(ww.x * W_SCALE);
    unsigned long long p1 = (1ULL << 40) + (unsigned long long)(ww.y * W_SCALE);
    unsigned long long prev0 = atomicAdd(&g_pack[cc.x], p0);
    unsigned long long prev1 = atomicAdd(&g_pack[cc.y], p1);
    uint2 rk = make_uint2((unsigned)(prev0 >> 40), (unsigned)(prev1 >> 40));
    *reinterpret_cast<uint2*>(g_rank + t * 2) = rk;
}

// fused: dinv + exclusive scan of counts (decoupled lookback)
__global__ void k_scan() {
    int t = threadIdx.x;
    int b = blockIdx.x;
    int i = b * SCAN_B + t;
    int lane = t & 31, wid = t >> 5;

    int cnt = 0;
    if (i < N_NODES) {
        unsigned long long p = g_pack[i];
        cnt = (int)(p >> 40);
        float deg = 1.0f + (float)(p & W_MASK) * (1.0f / W_SCALE);
        g_dinv[i] = rsqrtf(deg);
    }

    int v = cnt;
#pragma unroll
    for (int o = 1; o < 32; o <<= 1) {
        int y = __shfl_up_sync(0xffffffffu, v, o);
        if (lane >= o) v += y;
    }
    __shared__ int wsum[8];
    if (lane == 31) wsum[wid] = v;
    __syncthreads();
    if (wid == 0) {
        int x = (lane < 8) ? wsum[lane] : 0;
#pragma unroll
        for (int o = 1; o < 8; o <<= 1) {
            int y = __shfl_up_sync(0xffffffffu, x, o);
            if (lane >= o) x += y;
        }
        if (lane < 8) wsum[lane] = x;
    }
    __syncthreads();
    int incl = v + ((wid > 0) ? wsum[wid - 1] : 0);
    int blocktotal = wsum[7];

    __shared__ int sh_prefix;
    if (t == 0) {
        if (b == 0) {
            sh_prefix = 0;
            atomicExch(&g_scanstate[0], (2ULL << 62) | (unsigned)blocktotal);
        } else {
            atomicExch(&g_scanstate[b], (1ULL << 62) | (unsigned)blocktotal);
            int ex = 0;
            int j = b - 1;
            for (;;) {
                unsigned long long s;
                do { s = atomicAdd(&g_scanstate[j], 0ULL); } while ((s >> 62) == 0ULL);
                ex += (int)(s & 0xffffffffULL);
                if ((s >> 62) == 2ULL) break;
                j--;
            }
            sh_prefix = ex;
            atomicExch(&g_scanstate[b], (2ULL << 62) | (unsigned)(ex + blocktotal));
        }
    }
    __syncthreads();

    if (i < N_NODES) g_off[i] = sh_prefix + incl - cnt;   // exclusive
    if (i == 0) g_off[N_NODES] = N_EDGES;
}

// Interleaved roles: blockIdx%3==0 -> gemm block b/3; else fill block
// fidx = 2*(b/3) + (b%3) - 1. Extra tail fill slot is range-guarded.
__global__ void k_gemmfill(const float* __restrict__ x,
                           const float* __restrict__ W1,
                           const int* __restrict__ ei,
                           const float* __restrict__ w) {
    __shared__ float xs[GB][72];
    __shared__ float Ws[64][64];
    int t = threadIdx.x;
    int b = blockIdx.x;
    int rem = b % 3;

    if (rem != 0) {
        // ---- fill ----
        int fidx = (b / 3) * 2 + rem - 1;
        int t2 = fidx * 256 + t;
        if (t2 * 2 >= N_EDGES) return;
        int2   rr = *reinterpret_cast<const int2*>(ei + t2 * 2);
        int2   cc = *reinterpret_cast<const int2*>(ei + N_EDGES + t2 * 2);
        float2 ww = *reinterpret_cast<const float2*>(w + t2 * 2);
        uint2  rk = *reinterpret_cast<const uint2*>(g_rank + t2 * 2);
        int p0 = g_off[cc.x] + (int)rk.x;
        int p1 = g_off[cc.y] + (int)rk.y;
        g_edge[p0] = make_uint2((unsigned)rr.x, __float_as_uint(ww.x));
        g_edge[p1] = make_uint2((unsigned)rr.y, __float_as_uint(ww.y));
        return;
    }

    // ---- gemm ----
    int nb = (b / 3) * GB;
#pragma unroll
    for (int i = 0; i < 16; i++)
        ((float*)Ws)[t + i * 256] = W1[t + i * 256];
    {
        int nd = t >> 2;
        int q  = (t & 3) * 16;
        int node = nb + nd;
        if (node < N_NODES) {
            const float* xp = x + (size_t)node * 64 + q;
            float4 v0 = *(const float4*)(xp);
            float4 v1 = *(const float4*)(xp + 4);
            float4 v2 = *(const float4*)(xp + 8);
            float4 v3 = *(const float4*)(xp + 12);
            *(float4*)&xs[nd][q]      = v0;
            *(float4*)&xs[nd][q + 4]  = v1;
            *(float4*)&xs[nd][q + 8]  = v2;
            *(float4*)&xs[nd][q + 12] = v3;
        }
    }
    __syncthreads();

    int ch4 = (t & 15) * 4;
    int nd0 = (t >> 4) * 4;

    float acc[4][4];
#pragma unroll
    for (int i = 0; i < 4; i++)
#pragma unroll
        for (int j = 0; j < 4; j++) acc[i][j] = 0.0f;

#pragma unroll 4
    for (int k = 0; k < 64; k++) {
        float4 wv = *(const float4*)&Ws[k][ch4];
        float x0 = xs[nd0 + 0][k];
        float x1 = xs[nd0 + 1][k];
        float x2 = xs[nd0 + 2][k];
        float x3 = xs[nd0 + 3][k];
        acc[0][0] = fmaf(x0, wv.x, acc[0][0]); acc[0][1] = fmaf(x0, wv.y, acc[0][1]);
        acc[0][2] = fmaf(x0, wv.z, acc[0][2]); acc[0][3] = fmaf(x0, wv.w, acc[0][3]);
        acc[1][0] = fmaf(x1, wv.x, acc[1][0]); acc[1][1] = fmaf(x1, wv.y, acc[1][1]);
        acc[1][2] = fmaf(x1, wv.z, acc[1][2]); acc[1][3] = fmaf(x1, wv.w, acc[1][3]);
        acc[2][0] = fmaf(x2, wv.x, acc[2][0]); acc[2][1] = fmaf(x2, wv.y, acc[2][1]);
        acc[2][2] = fmaf(x2, wv.z, acc[2][2]); acc[2][3] = fmaf(x2, wv.w, acc[2][3]);
        acc[3][0] = fmaf(x3, wv.x, acc[3][0]); acc[3][1] = fmaf(x3, wv.y, acc[3][1]);
        acc[3][2] = fmaf(x3, wv.z, acc[3][2]); acc[3][3] = fmaf(x3, wv.w, acc[3][3]);
    }

#pragma unroll
    for (int i = 0; i < 4; i++) {
        int node = nb + nd0 + i;
        if (node < N_NODES) {
            float di = g_dinv[node];
            __half2 p0 = __floats2half2_rn(acc[i][0] * di, acc[i][1] * di);
            __half2 p1 = __floats2half2_rn(acc[i][2] * di, acc[i][3] * di);
            uint2 st = make_uint2(h2_bits(p0), h2_bits(p1));
            *reinterpret_cast<uint2*>(g_hh + (size_t)node * 64 + ch4) = st;
        }
    }
}

// fused layer1 aggregate + relu + layer2 projection. one warp per node.
// quarter-warp per edge: 8 lanes x uint4 (8 fp16) = full 128B row.
__global__ void k_layer1(const float* __restrict__ b1,
                         const float* __restrict__ W2) {
    int n = (blockIdx.x * blockDim.x + threadIdx.x) >> 5;
    int lane = threadIdx.x & 31;
    if (n >= N_NODES) return;
    int quarter = lane >> 3;
    int sub     = lane & 7;

    int idx = g_off[n];
    int end = g_off[n + 1];
    const uint4* __restrict__ hp = reinterpret_cast<const uint4*>(g_hh);

    float a[8];
#pragma unroll
    for (int j = 0; j < 8; j++) a[j] = 0.0f;

    for (; idx + 8 <= end; idx += 8) {
        uint2 ea = g_edge[idx + quarter];
        uint2 eb = g_edge[idx + 4 + quarter];
        uint4 hva = hp[ea.x * 8u + sub];
        uint4 hvb = hp[eb.x * 8u + sub];
        float ca = __uint_as_float(ea.y);
        float cb = __uint_as_float(eb.y);
        float2 a0 = __half22float2(*reinterpret_cast<__half2*>(&hva.x));
        float2 a1 = __half22float2(*reinterpret_cast<__half2*>(&hva.y));
        float2 a2 = __half22float2(*reinterpret_cast<__half2*>(&hva.z));
        float2 a3 = __half22float2(*reinterpret_cast<__half2*>(&hva.w));
        float2 b0 = __half22float2(*reinterpret_cast<__half2*>(&hvb.x));
        float2 b1v = __half22float2(*reinterpret_cast<__half2*>(&hvb.y));
        float2 b2v = __half22float2(*reinterpret_cast<__half2*>(&hvb.z));
        float2 b3 = __half22float2(*reinterpret_cast<__half2*>(&hvb.w));
        a[0] = fmaf(ca, a0.x, a[0]); a[1] = fmaf(ca, a0.y, a[1]);
        a[2] = fmaf(ca, a1.x, a[2]); a[3] = fmaf(ca, a1.y, a[3]);
        a[4] = fmaf(ca, a2.x, a[4]); a[5] = fmaf(ca, a2.y, a[5]);
        a[6] = fmaf(ca, a3.x, a[6]); a[7] = fmaf(ca, a3.y, a[7]);
        a[0] = fmaf(cb, b0.x, a[0]); a[1] = fmaf(cb, b0.y, a[1]);
        a[2] = fmaf(cb, b1v.x, a[2]); a[3] = fmaf(cb, b1v.y, a[3]);
        a[4] = fmaf(cb, b2v.x, a[4]); a[5] = fmaf(cb, b2v.y, a[5]);
        a[6] = fmaf(cb, b3.x, a[6]); a[7] = fmaf(cb, b3.y, a[7]);
    }
    if (idx + 4 <= end) {
        uint2 e = g_edge[idx + quarter];
        uint4 hv = hp[e.x * 8u + sub];
        float cf = __uint_as_float(e.y);
        float2 f0 = __half22float2(*reinterpret_cast<__half2*>(&hv.x));
        float2 f1 = __half22float2(*reinterpret_cast<__half2*>(&hv.y));
        float2 f2 = __half22float2(*reinterpret_cast<__half2*>(&hv.z));
        float2 f3 = __half22float2(*reinterpret_cast<__half2*>(&hv.w));
        a[0] = fmaf(cf, f0.x, a[0]); a[1] = fmaf(cf, f0.y, a[1]);
        a[2] = fmaf(cf, f1.x, a[2]); a[3] = fmaf(cf, f1.y, a[3]);
        a[4] = fmaf(cf, f2.x, a[4]); a[5] = fmaf(cf, f2.y, a[5]);
        a[6] = fmaf(cf, f3.x, a[6]); a[7] = fmaf(cf, f3.y, a[7]);
        idx += 4;
    }
    if (idx < end) {
        int my = idx + quarter;
        if (my < end) {
            uint2 e = g_edge[my];
            uint4 hv = hp[e.x * 8u + sub];
            float cf = __uint_as_float(e.y);
            float2 f0 = __half22float2(*reinterpret_cast<__half2*>(&hv.x));
            float2 f1 = __half22float2(*reinterpret_cast<__half2*>(&hv.y));
            float2 f2 = __half22float2(*reinterpret_cast<__half2*>(&hv.z));
            float2 f3 = __half22float2(*reinterpret_cast<__half2*>(&hv.w));
            a[0] = fmaf(cf, f0.x, a[0]); a[1] = fmaf(cf, f0.y, a[1]);
            a[2] = fmaf(cf, f1.x, a[2]); a[3] = fmaf(cf, f1.y, a[3]);
            a[4] = fmaf(cf, f2.x, a[4]); a[5] = fmaf(cf, f2.y, a[5]);
            a[6] = fmaf(cf, f3.x, a[6]); a[7] = fmaf(cf, f3.y, a[7]);
        }
    }

#pragma unroll
    for (int j = 0; j < 8; j++) {
        a[j] += __shfl_xor_sync(0xffffffffu, a[j], 8);
        a[j] += __shfl_xor_sync(0xffffffffu, a[j], 16);
    }

    float din = g_dinv[n];
    uint4 hnv = hp[(unsigned)n * 8u + sub];
    float2 hn0 = __half22float2(*reinterpret_cast<__half2*>(&hnv.x));
    float2 hn1 = __half22float2(*reinterpret_cast<__half2*>(&hnv.y));
    float2 hn2 = __half22float2(*reinterpret_cast<__half2*>(&hnv.z));
    float2 hn3 = __half22float2(*reinterpret_cast<__half2*>(&hnv.w));
    float hn[8] = {hn0.x, hn0.y, hn1.x, hn1.y, hn2.x, hn2.y, hn3.x, hn3.y};

    float4 bA = reinterpret_cast<const float4*>(b1)[sub * 2];
    float4 bB = reinterpret_cast<const float4*>(b1)[sub * 2 + 1];
    float4 wA = reinterpret_cast<const float4*>(W2)[sub * 2];
    float4 wB = reinterpret_cast<const float4*>(W2)[sub * 2 + 1];
    float bb[8] = {bA.x, bA.y, bA.z, bA.w, bB.x, bB.y, bB.z, bB.w};
    float w2[8] = {wA.x, wA.y, wA.z, wA.w, wB.x, wB.y, wB.z, wB.w};

    float s = 0.0f;
#pragma unroll
    for (int j = 0; j < 8; j++) {
        float v = fmaxf(fmaf(a[j] + hn[j], din, bb[j]), 0.0f);
        s = fmaf(v, w2[j], s);
    }
#pragma unroll
    for (int off = 4; off > 0; off >>= 1)
        s += __shfl_xor_sync(0xffffffffu, s, off);
    if (lane == 0) g_s[n] = s * din;   // store s' = s*dinv
}

// layer2 gather: 8 lanes per node (4 nodes/warp); also re-zeroes
// g_pack/g_scanstate so the next call starts from clean state.
__global__ void k_layer2(const float* __restrict__ b2,
                         float* __restrict__ out) {
    int gtid = blockIdx.x * blockDim.x + threadIdx.x;
    if (gtid < N_NODES) g_pack[gtid] = 0ULL;
    if (gtid < NB) g_scanstate[gtid] = 0ULL;

    int n = gtid >> 3;
    int sub = threadIdx.x & 7;
    if (n >= N_NODES) return;

    int begin = g_off[n];
    int end   = g_off[n + 1];

    float acc = 0.0f;
    for (int idx = begin + sub; idx < end; idx += 8) {
        uint2 em = g_edge[idx];
        acc = fmaf(__uint_as_float(em.y), g_s[em.x], acc);
    }
#pragma unroll
    for (int off = 4; off > 0; off >>= 1)
        acc += __shfl_xor_sync(0xffffffffu, acc, off);

    if (sub == 0) {
        float din = g_dinv[n];
        out[n] = fmaf(acc + g_s[n], din, b2[0]);
    }
}

extern "C" void kernel_launch(void* const* d_in, const int* in_sizes, int n_in,
                              void* d_out, int out_size) {
    const float* x  = (const float*)d_in[0];
    const int*   ei = (const int*)d_in[1];
    const float* w  = (const float*)d_in[2];
    const float* W1 = (const float*)d_in[3];
    const float* b1 = (const float*)d_in[4];
    const float* W2 = (const float*)d_in[5];
    const float* b2 = (const float*)d_in[6];
    float* out = (float*)d_out;

    const int T = 256;
    k_edge_count<<<(N_EDGES / 2 + T - 1) / T, T>>>(ei, w);
    k_scan<<<NB, SCAN_B>>>();
    k_gemmfill<<<GF_GRID, T>>>(x, W1, ei, w);
    k_layer1<<<(N_NODES * 32 + T - 1) / T, T>>>(b1, W2);
    k_layer2<<<(N_NODES * 8 + T - 1) / T, T>>>(b2, out);
}

// round 14
// speedup vs baseline: 1.0067x; 1.0067x over previous
#include <cuda_runtime.h>
#include <cuda_fp16.h>

// 2-layer GCN via CSC build + gather aggregation.
// edge_index arrives as int32 (JAX x64 disabled).
// h' = (x@W1)*dinv stored FP16 (128B/row), fp32 accumulation, s' = s*dinv.
// No init kernel: device globals start zeroed; k_layer2 re-zeroes
// g_pack/g_scanstate at the end of every call.
// Layer kernels use 64-thread CTAs to kill intra-CTA degree imbalance
// (Poisson(16) degrees: max-of-8 warps wastes ~60%, max-of-2 only ~18%).

#define N_NODES 100000
#define N_EDGES 1600000
#define C 64
#define SCAN_B 256
#define NB ((N_NODES + SCAN_B - 1) / SCAN_B)   // 391
#define W_SCALE 67108864.0f                    // 2^26 fixed-point for w
#define W_MASK  ((1ULL << 40) - 1ULL)
#define GB 64
#define GEMM_GRID ((N_NODES + GB - 1) / GB)    // 1563
#define GF_GRID (GEMM_GRID * 3)                // 4689

__device__ unsigned long long g_pack[N_NODES];   // {cnt:24 | sum_w fixed:40}
__device__ float g_dinv[N_NODES];
__device__ int   g_off[N_NODES + 1];
__device__ unsigned long long g_scanstate[NB];   // {flag:2 | value:32}
__device__ __align__(16) unsigned g_rank[N_EDGES];
__device__ __align__(16) uint2 g_edge[N_EDGES];            // {src, w bits}
__device__ __align__(16) __half g_hh[(size_t)N_NODES * C]; // h' fp16, 128B/row
__device__ float g_s[N_NODES];                             // s' = s*dinv

__device__ __forceinline__ unsigned h2_bits(__half2 v) {
    return *reinterpret_cast<unsigned*>(&v);
}

// one packed u64 atomic per edge; prev count == rank within destination bucket
__global__ void k_edge_count(const int* __restrict__ ei,
                             const float* __restrict__ w) {
    int t = blockIdx.x * blockDim.x + threadIdx.x;
    if (t * 2 >= N_EDGES) return;
    int2   cc = *reinterpret_cast<const int2*>(ei + N_EDGES + t * 2);
    float2 ww = *reinterpret_cast<const float2*>(w + t * 2);
    unsigned long long p0 = (1ULL << 40) + (unsigned long long)(ww.x * W_SCALE);
    unsigned long long p1 = (1ULL << 40) + (unsigned long long)(ww.y * W_SCALE);
    unsigned long long prev0 = atomicAdd(&g_pack[cc.x], p0);
    unsigned long long prev1 = atomicAdd(&g_pack[cc.y], p1);
    uint2 rk = make_uint2((unsigned)(prev0 >> 40), (unsigned)(prev1 >> 40));
    *reinterpret_cast<uint2*>(g_rank + t * 2) = rk;
}

// fused: dinv + exclusive scan of counts (decoupled lookback)
__global__ void k_scan() {
    int t = threadIdx.x;
    int b = blockIdx.x;
    int i = b * SCAN_B + t;
    int lane = t & 31, wid = t >> 5;

    int cnt = 0;
    if (i < N_NODES) {
        unsigned long long p = g_pack[i];
        cnt = (int)(p >> 40);
        float deg = 1.0f + (float)(p & W_MASK) * (1.0f / W_SCALE);
        g_dinv[i] = rsqrtf(deg);
    }

    int v = cnt;
#pragma unroll
    for (int o = 1; o < 32; o <<= 1) {
        int y = __shfl_up_sync(0xffffffffu, v, o);
        if (lane >= o) v += y;
    }
    __shared__ int wsum[8];
    if (lane == 31) wsum[wid] = v;
    __syncthreads();
    if (wid == 0) {
        int x = (lane < 8) ? wsum[lane] : 0;
#pragma unroll
        for (int o = 1; o < 8; o <<= 1) {
            int y = __shfl_up_sync(0xffffffffu, x, o);
            if (lane >= o) x += y;
        }
        if (lane < 8) wsum[lane] = x;
    }
    __syncthreads();
    int incl = v + ((wid > 0) ? wsum[wid - 1] : 0);
    int blocktotal = wsum[7];

    __shared__ int sh_prefix;
    if (t == 0) {
        if (b == 0) {
            sh_prefix = 0;
            atomicExch(&g_scanstate[0], (2ULL << 62) | (unsigned)blocktotal);
        } else {
            atomicExch(&g_scanstate[b], (1ULL << 62) | (unsigned)blocktotal);
            int ex = 0;
            int j = b - 1;
            for (;;) {
                unsigned long long s;
                do { s = atomicAdd(&g_scanstate[j], 0ULL); } while ((s >> 62) == 0ULL);
                ex += (int)(s & 0xffffffffULL);
                if ((s >> 62) == 2ULL) break;
                j--;
            }
            sh_prefix = ex;
            atomicExch(&g_scanstate[b], (2ULL << 62) | (unsigned)(ex + blocktotal));
        }
    }
    __syncthreads();

    if (i < N_NODES) g_off[i] = sh_prefix + incl - cnt;   // exclusive
    if (i == 0) g_off[N_NODES] = N_EDGES;
}

// Interleaved roles: blockIdx%3==0 -> gemm block b/3; else fill block.
__global__ void k_gemmfill(const float* __restrict__ x,
                           const float* __restrict__ W1,
                           const int* __restrict__ ei,
                           const float* __restrict__ w) {
    __shared__ float xs[GB][72];
    __shared__ float Ws[64][64];
    int t = threadIdx.x;
    int b = blockIdx.x;
    int rem = b % 3;

    if (rem != 0) {
        int fidx = (b / 3) * 2 + rem - 1;
        int t2 = fidx * 256 + t;
        if (t2 * 2 >= N_EDGES) return;
        int2   rr = *reinterpret_cast<const int2*>(ei + t2 * 2);
        int2   cc = *reinterpret_cast<const int2*>(ei + N_EDGES + t2 * 2);
        float2 ww = *reinterpret_cast<const float2*>(w + t2 * 2);
        uint2  rk = *reinterpret_cast<const uint2*>(g_rank + t2 * 2);
        int p0 = g_off[cc.x] + (int)rk.x;
        int p1 = g_off[cc.y] + (int)rk.y;
        g_edge[p0] = make_uint2((unsigned)rr.x, __float_as_uint(ww.x));
        g_edge[p1] = make_uint2((unsigned)rr.y, __float_as_uint(ww.y));
        return;
    }

    int nb = (b / 3) * GB;
#pragma unroll
    for (int i = 0; i < 16; i++)
        ((float*)Ws)[t + i * 256] = W1[t + i * 256];
    {
        int nd = t >> 2;
        int q  = (t & 3) * 16;
        int node = nb + nd;
        if (node < N_NODES) {
            const float* xp = x + (size_t)node * 64 + q;
            float4 v0 = *(const float4*)(xp);
            float4 v1 = *(const float4*)(xp + 4);
            float4 v2 = *(const float4*)(xp + 8);
            float4 v3 = *(const float4*)(xp + 12);
            *(float4*)&xs[nd][q]      = v0;
            *(float4*)&xs[nd][q + 4]  = v1;
            *(float4*)&xs[nd][q + 8]  = v2;
            *(float4*)&xs[nd][q + 12] = v3;
        }
    }
    __syncthreads();

    int ch4 = (t & 15) * 4;
    int nd0 = (t >> 4) * 4;

    float acc[4][4];
#pragma unroll
    for (int i = 0; i < 4; i++)
#pragma unroll
        for (int j = 0; j < 4; j++) acc[i][j] = 0.0f;

#pragma unroll 4
    for (int k = 0; k < 64; k++) {
        float4 wv = *(const float4*)&Ws[k][ch4];
        float x0 = xs[nd0 + 0][k];
        float x1 = xs[nd0 + 1][k];
        float x2 = xs[nd0 + 2][k];
        float x3 = xs[nd0 + 3][k];
        acc[0][0] = fmaf(x0, wv.x, acc[0][0]); acc[0][1] = fmaf(x0, wv.y, acc[0][1]);
        acc[0][2] = fmaf(x0, wv.z, acc[0][2]); acc[0][3] = fmaf(x0, wv.w, acc[0][3]);
        acc[1][0] = fmaf(x1, wv.x, acc[1][0]); acc[1][1] = fmaf(x1, wv.y, acc[1][1]);
        acc[1][2] = fmaf(x1, wv.z, acc[1][2]); acc[1][3] = fmaf(x1, wv.w, acc[1][3]);
        acc[2][0] = fmaf(x2, wv.x, acc[2][0]); acc[2][1] = fmaf(x2, wv.y, acc[2][1]);
        acc[2][2] = fmaf(x2, wv.z, acc[2][2]); acc[2][3] = fmaf(x2, wv.w, acc[2][3]);
        acc[3][0] = fmaf(x3, wv.x, acc[3][0]); acc[3][1] = fmaf(x3, wv.y, acc[3][1]);
        acc[3][2] = fmaf(x3, wv.z, acc[3][2]); acc[3][3] = fmaf(x3, wv.w, acc[3][3]);
    }

#pragma unroll
    for (int i = 0; i < 4; i++) {
        int node = nb + nd0 + i;
        if (node < N_NODES) {
            float di = g_dinv[node];
            __half2 p0 = __floats2half2_rn(acc[i][0] * di, acc[i][1] * di);
            __half2 p1 = __floats2half2_rn(acc[i][2] * di, acc[i][3] * di);
            uint2 st = make_uint2(h2_bits(p0), h2_bits(p1));
            *reinterpret_cast<uint2*>(g_hh + (size_t)node * 64 + ch4) = st;
        }
    }
}

// fused layer1 aggregate + relu + layer2 projection. one warp per node.
// 64-thread CTAs (2 nodes) to minimize intra-CTA degree-imbalance waste.
__global__ void k_layer1(const float* __restrict__ b1,
                         const float* __restrict__ W2) {
    int n = (blockIdx.x * blockDim.x + threadIdx.x) >> 5;
    int lane = threadIdx.x & 31;
    if (n >= N_NODES) return;
    int quarter = lane >> 3;
    int sub     = lane & 7;

    int idx = g_off[n];
    int end = g_off[n + 1];
    const uint4* __restrict__ hp = reinterpret_cast<const uint4*>(g_hh);

    float a[8];
#pragma unroll
    for (int j = 0; j < 8; j++) a[j] = 0.0f;

    for (; idx + 8 <= end; idx += 8) {
        uint2 ea = g_edge[idx + quarter];
        uint2 eb = g_edge[idx + 4 + quarter];
        uint4 hva = hp[ea.x * 8u + sub];
        uint4 hvb = hp[eb.x * 8u + sub];
        float ca = __uint_as_float(ea.y);
        float cb = __uint_as_float(eb.y);
        float2 a0 = __half22float2(*reinterpret_cast<__half2*>(&hva.x));
        float2 a1 = __half22float2(*reinterpret_cast<__half2*>(&hva.y));
        float2 a2 = __half22float2(*reinterpret_cast<__half2*>(&hva.z));
        float2 a3 = __half22float2(*reinterpret_cast<__half2*>(&hva.w));
        float2 b0 = __half22float2(*reinterpret_cast<__half2*>(&hvb.x));
        float2 b1v = __half22float2(*reinterpret_cast<__half2*>(&hvb.y));
        float2 b2v = __half22float2(*reinterpret_cast<__half2*>(&hvb.z));
        float2 b3 = __half22float2(*reinterpret_cast<__half2*>(&hvb.w));
        a[0] = fmaf(ca, a0.x, a[0]); a[1] = fmaf(ca, a0.y, a[1]);
        a[2] = fmaf(ca, a1.x, a[2]); a[3] = fmaf(ca, a1.y, a[3]);
        a[4] = fmaf(ca, a2.x, a[4]); a[5] = fmaf(ca, a2.y, a[5]);
        a[6] = fmaf(ca, a3.x, a[6]); a[7] = fmaf(ca, a3.y, a[7]);
        a[0] = fmaf(cb, b0.x, a[0]); a[1] = fmaf(cb, b0.y, a[1]);
        a[2] = fmaf(cb, b1v.x, a[2]); a[3] = fmaf(cb, b1v.y, a[3]);
        a[4] = fmaf(cb, b2v.x, a[4]); a[5] = fmaf(cb, b2v.y, a[5]);
        a[6] = fmaf(cb, b3.x, a[6]); a[7] = fmaf(cb, b3.y, a[7]);
    }
    if (idx + 4 <= end) {
        uint2 e = g_edge[idx + quarter];
        uint4 hv = hp[e.x * 8u + sub];
        float cf = __uint_as_float(e.y);
        float2 f0 = __half22float2(*reinterpret_cast<__half2*>(&hv.x));
        float2 f1 = __half22float2(*reinterpret_cast<__half2*>(&hv.y));
        float2 f2 = __half22float2(*reinterpret_cast<__half2*>(&hv.z));
        float2 f3 = __half22float2(*reinterpret_cast<__half2*>(&hv.w));
        a[0] = fmaf(cf, f0.x, a[0]); a[1] = fmaf(cf, f0.y, a[1]);
        a[2] = fmaf(cf, f1.x, a[2]); a[3] = fmaf(cf, f1.y, a[3]);
        a[4] = fmaf(cf, f2.x, a[4]); a[5] = fmaf(cf, f2.y, a[5]);
        a[6] = fmaf(cf, f3.x, a[6]); a[7] = fmaf(cf, f3.y, a[7]);
        idx += 4;
    }
    if (idx < end) {
        int my = idx + quarter;
        if (my < end) {
            uint2 e = g_edge[my];
            uint4 hv = hp[e.x * 8u + sub];
            float cf = __uint_as_float(e.y);
            float2 f0 = __half22float2(*reinterpret_cast<__half2*>(&hv.x));
            float2 f1 = __half22float2(*reinterpret_cast<__half2*>(&hv.y));
            float2 f2 = __half22float2(*reinterpret_cast<__half2*>(&hv.z));
            float2 f3 = __half22float2(*reinterpret_cast<__half2*>(&hv.w));
            a[0] = fmaf(cf, f0.x, a[0]); a[1] = fmaf(cf, f0.y, a[1]);
            a[2] = fmaf(cf, f1.x, a[2]); a[3] = fmaf(cf, f1.y, a[3]);
            a[4] = fmaf(cf, f2.x, a[4]); a[5] = fmaf(cf, f2.y, a[5]);
            a[6] = fmaf(cf, f3.x, a[6]); a[7] = fmaf(cf, f3.y, a[7]);
        }
    }

#pragma unroll
    for (int j = 0; j < 8; j++) {
        a[j] += __shfl_xor_sync(0xffffffffu, a[j], 8);
        a[j] += __shfl_xor_sync(0xffffffffu, a[j], 16);
    }

    float din = g_dinv[n];
    uint4 hnv = hp[(unsigned)n * 8u + sub];
    float2 hn0 = __half22float2(*reinterpret_cast<__half2*>(&hnv.x));
    float2 hn1 = __half22float2(*reinterpret_cast<__half2*>(&hnv.y));
    float2 hn2 = __half22float2(*reinterpret_cast<__half2*>(&hnv.z));
    float2 hn3 = __half22float2(*reinterpret_cast<__half2*>(&hnv.w));
    float hn[8] = {hn0.x, hn0.y, hn1.x, hn1.y, hn2.x, hn2.y, hn3.x, hn3.y};

    float4 bA = reinterpret_cast<const float4*>(b1)[sub * 2];
    float4 bB = reinterpret_cast<const float4*>(b1)[sub * 2 + 1];
    float4 wA = reinterpret_cast<const float4*>(W2)[sub * 2];
    float4 wB = reinterpret_cast<const float4*>(W2)[sub * 2 + 1];
    float bb[8] = {bA.x, bA.y, bA.z, bA.w, bB.x, bB.y, bB.z, bB.w};
    float w2[8] = {wA.x, wA.y, wA.z, wA.w, wB.x, wB.y, wB.z, wB.w};

    float s = 0.0f;
#pragma unroll
    for (int j = 0; j < 8; j++) {
        float v = fmaxf(fmaf(a[j] + hn[j], din, bb[j]), 0.0f);
        s = fmaf(v, w2[j], s);
    }
#pragma unroll
    for (int off = 4; off > 0; off >>= 1)
        s += __shfl_xor_sync(0xffffffffu, s, off);
    if (lane == 0) g_s[n] = s * din;   // store s' = s*dinv
}

// layer2 gather: 8 lanes per node; 64-thread CTAs; also re-zeroes
// g_pack/g_scanstate so the next call starts from clean state.
__global__ void k_layer2(const float* __restrict__ b2,
                         float* __restrict__ out) {
    int gtid = blockIdx.x * blockDim.x + threadIdx.x;
    if (gtid < N_NODES) g_pack[gtid] = 0ULL;
    if (gtid < NB) g_scanstate[gtid] = 0ULL;

    int n = gtid >> 3;
    int sub = threadIdx.x & 7;
    if (n >= N_NODES) return;

    int begin = g_off[n];
    int end   = g_off[n + 1];

    float acc = 0.0f;
    for (int idx = begin + sub; idx < end; idx += 8) {
        uint2 em = g_edge[idx];
        acc = fmaf(__uint_as_float(em.y), g_s[em.x], acc);
    }
#pragma unroll
    for (int off = 4; off > 0; off >>= 1)
        acc += __shfl_xor_sync(0xffffffffu, acc, off);

    if (sub == 0) {
        float din = g_dinv[n];
        out[n] = fmaf(acc + g_s[n], din, b2[0]);
    }
}

extern "C" void kernel_launch(void* const* d_in, const int* in_sizes, int n_in,
                              void* d_out, int out_size) {
    const float* x  = (const float*)d_in[0];
    const int*   ei = (const int*)d_in[1];
    const float* w  = (const float*)d_in[2];
    const float* W1 = (const float*)d_in[3];
    const float* b1 = (const float*)d_in[4];
    const float* W2 = (const float*)d_in[5];
    const float* b2 = (const float*)d_in[6];
    float* out = (float*)d_out;

    const int T = 256;
    k_edge_count<<<(N_EDGES / 2 + T - 1) / T, T>>>(ei, w);
    k_scan<<<NB, SCAN_B>>>();
    k_gemmfill<<<GF_GRID, T>>>(x, W1, ei, w);
    k_layer1<<<(N_NODES * 32 + 63) / 64, 64>>>(b1, W2);
    k_layer2<<<(N_NODES * 8 + 63) / 64, 64>>>(b2, out);
}